// round 8
// baseline (speedup 1.0000x reference)
#include <cuda_runtime.h>
#include <cuda_fp16.h>
#include <cstdint>

// Problem constants
#define Cdim 2048
#define Sdim 2048
#define Bdim 4
#define Hdim 16
#define Ddim 128
#define Mtok (Bdim * Sdim)          // 8192
#define QKV_N (3 * Cdim)            // 6144

// ---------------------------------------------------------------------------
// Scratch (device globals — no allocation allowed)
// ---------------------------------------------------------------------------
__device__ __half g_qkvh[(size_t)Mtok * QKV_N];      // qkv hi (fp16)
__device__ __half g_qkvl[(size_t)Mtok * QKV_N];      // qkv lo (fp16)
__device__ __half g_xh[(size_t)Mtok * Cdim];
__device__ __half g_xl[(size_t)Mtok * Cdim];
__device__ __half g_yh[(size_t)Mtok * Cdim];
__device__ __half g_yl[(size_t)Mtok * Cdim];
__device__ __half g_wqkvT[(size_t)QKV_N * Cdim];     // [6144, 2048] (N,K) fp16
__device__ __half g_wprojT[(size_t)Cdim * Cdim];     // [2048, 2048] fp16

// ---------------------------------------------------------------------------
// PTX helpers (base-ISA only: cp.async / ldmatrix / mma.sync)
// ---------------------------------------------------------------------------
__device__ __forceinline__ uint32_t smem_u32(const void* p) {
    uint32_t a;
    asm("{ .reg .u64 t; cvta.to.shared.u64 t, %1; cvt.u32.u64 %0, t; }" : "=r"(a) : "l"(p));
    return a;
}

#define CP_ASYNC16(dst, src) \
    asm volatile("cp.async.cg.shared.global [%0], [%1], 16;" :: "r"(dst), "l"(src))
#define CP_COMMIT() asm volatile("cp.async.commit_group;" ::: "memory")
#define CP_WAIT(n)  asm volatile("cp.async.wait_group %0;" :: "n"(n) : "memory")

__device__ __forceinline__ void ldsm4(uint32_t* r, uint32_t addr) {
    asm volatile("ldmatrix.sync.aligned.m8n8.x4.shared.b16 {%0,%1,%2,%3}, [%4];"
                 : "=r"(r[0]), "=r"(r[1]), "=r"(r[2]), "=r"(r[3]) : "r"(addr));
}
__device__ __forceinline__ void ldsm4t(uint32_t* r, uint32_t addr) {
    asm volatile("ldmatrix.sync.aligned.m8n8.x4.trans.shared.b16 {%0,%1,%2,%3}, [%4];"
                 : "=r"(r[0]), "=r"(r[1]), "=r"(r[2]), "=r"(r[3]) : "r"(addr));
}

// fp16 MMA, fp32 accumulate
__device__ __forceinline__ void mma16816(float* d, const uint32_t* a,
                                         uint32_t b0, uint32_t b1) {
    asm volatile(
        "mma.sync.aligned.m16n8k16.row.col.f32.f16.f16.f32 "
        "{%0,%1,%2,%3}, {%4,%5,%6,%7}, {%8,%9}, {%0,%1,%2,%3};"
        : "+f"(d[0]), "+f"(d[1]), "+f"(d[2]), "+f"(d[3])
        : "r"(a[0]), "r"(a[1]), "r"(a[2]), "r"(a[3]), "r"(b0), "r"(b1));
}

// pack two fp32 -> fp16x2 (first arg in low half)
__device__ __forceinline__ uint32_t pack_f16(float lo, float hi) {
    uint32_t r;
    asm("cvt.rn.f16x2.f32 %0, %1, %2;" : "=r"(r) : "f"(hi), "f"(lo));
    return r;
}
__device__ __forceinline__ float2 unpack_f16(uint32_t pk) {
    __half2 h = *reinterpret_cast<__half2*>(&pk);
    return make_float2(__low2float(h), __high2float(h));
}

// ---------------------------------------------------------------------------
// Conversion kernels
// ---------------------------------------------------------------------------
__global__ void split_kernel(const float* __restrict__ in,
                             __half* __restrict__ hi,
                             __half* __restrict__ lo, int n)
{
    int i = (blockIdx.x * blockDim.x + threadIdx.x) * 4;
    if (i >= n) return;
    float4 v = *(const float4*)(in + i);
    float vv[4] = {v.x, v.y, v.z, v.w};
    uint32_t hp[2], lp[2];
#pragma unroll
    for (int p = 0; p < 2; ++p) {
        uint32_t pk = pack_f16(vv[2 * p], vv[2 * p + 1]);
        float2 r = unpack_f16(pk);
        hp[p] = pk;
        lp[p] = pack_f16(vv[2 * p] - r.x, vv[2 * p + 1] - r.y);
    }
    *(uint2*)(hi + i) = make_uint2(hp[0], hp[1]);
    *(uint2*)(lo + i) = make_uint2(lp[0], lp[1]);
}

// W [K, N] fp32 -> Wt [N, K] fp16 (single-term B side)
__global__ void transpose_h_kernel(const float* __restrict__ W,
                                   __half* __restrict__ Th, int K, int N)
{
    __shared__ float tile[32][33];
    int n0 = blockIdx.x * 32, k0 = blockIdx.y * 32;
    int tx = threadIdx.x, ty = threadIdx.y;   // 32 x 8
#pragma unroll
    for (int j = 0; j < 32; j += 8)
        tile[ty + j][tx] = W[(size_t)(k0 + ty + j) * N + n0 + tx];
    __syncthreads();
#pragma unroll
    for (int j = 0; j < 32; j += 8)
        Th[(size_t)(n0 + ty + j) * K + k0 + tx] = __float2half(tile[tx][ty + j]);
}

// ---------------------------------------------------------------------------
// fp16x2 GEMM: C[M,N] = (Ah+Al) @ Bh^T + bias. CTA tile 128x128, BK=32,
// 4 warps (2m x 2n) with 64x64 warp tiles, 4-stage cp.async, 2 CTAs/SM.
// Precomputed ldsm/cp.async addresses; k16 step via XOR 0x20.
// OUTM=0: fp32 C.  OUTM=1: split fp16 (Ch, Cl).
// ---------------------------------------------------------------------------
#define GA_TILE 8192                       // 128 x 32 fp16 = 8 KB
#define GSTAGE (3 * GA_TILE)               // Ah, Al, B = 24 KB
#define GEMM_SMEM (4 * GSTAGE + 128)       // + alignment slack

template<int OUTM>
__global__ __launch_bounds__(128, 2) void gemm_mma_kernel(
    const __half* __restrict__ Ah, const __half* __restrict__ Al,
    const __half* __restrict__ Bh,
    const float* __restrict__ bias, float* __restrict__ C,
    __half* __restrict__ Ch, __half* __restrict__ Cl,
    int M, int N, int K)
{
    extern __shared__ char smem[];
    const uint32_t sbase = (smem_u32(smem) + 127u) & ~127u;   // 128B aligned

    const int t   = threadIdx.x;            // 0..127
    const int wid = t >> 5;                  // 0..3
    const int lid = t & 31;
    const int n0  = blockIdx.x * 128;
    const int m0  = blockIdx.y * 128;
    const int wm  = (wid & 1) * 64;          // 2m x 2n warp grid, 64x64 tiles
    const int wn  = (wid >> 1) * 64;

    // ---- cp.async precompute: each thread owns (row,j); 4 slots per tensor,
    //      slots step +32 rows (src += 32*K halfs, dst += 2048 B) ----
    const int lrow = t >> 2;                 // 0..31
    const int lj   = t & 3;                  // 16B-group
    const __half* srcP[3] = {
        Ah + (size_t)(m0 + lrow) * K + lj * 8,
        Al + (size_t)(m0 + lrow) * K + lj * 8,
        Bh + (size_t)(n0 + lrow) * K + lj * 8 };
    const uint32_t dRow = lrow * 64 + ((lj ^ ((lrow >> 1) & 3)) << 4);
    const uint32_t dOff[3] = { dRow, GA_TILE + dRow, 2u * GA_TILE + dRow };

    // ---- ldsm address precompute (stage-relative, jg = lk) ----
    const int lrow8 = (lid & 7) + ((lid >> 3) & 1) * 8;
    const int lk    = (lid >> 4) & 1;
    uint32_t aoffH[4], aoffL[4], boff[4];
#pragma unroll
    for (int mt = 0; mt < 4; ++mt) {
        int r = wm + mt * 16 + lrow8;
        uint32_t o = r * 64 + ((lk ^ ((r >> 1) & 3)) << 4);
        aoffH[mt] = o;
        aoffL[mt] = GA_TILE + o;
    }
#pragma unroll
    for (int nb = 0; nb < 4; ++nb) {
        int r = wn + nb * 16 + lrow8;
        boff[nb] = 2u * GA_TILE + r * 64 + ((lk ^ ((r >> 1) & 3)) << 4);
    }

    float acc[4][8][4];
#pragma unroll
    for (int mt = 0; mt < 4; ++mt)
#pragma unroll
        for (int nt = 0; nt < 8; ++nt)
#pragma unroll
            for (int e = 0; e < 4; ++e) acc[mt][nt][e] = 0.f;

    auto load_stage = [&](int stage, int kOff) {
        uint32_t sb = sbase + stage * GSTAGE;
#pragma unroll
        for (int p = 0; p < 3; ++p) {
            const __half* s = srcP[p] + kOff;
            uint32_t d = sb + dOff[p];
#pragma unroll
            for (int i = 0; i < 4; ++i)
                CP_ASYNC16(d + i * 2048, s + (size_t)i * 32 * K);
        }
    };

    const int nk = K / 32;                  // 64 chunks
    load_stage(0, 0);  CP_COMMIT();
    load_stage(1, 32); CP_COMMIT();
    load_stage(2, 64); CP_COMMIT();

    for (int c = 0; c < nk; ++c) {
        CP_WAIT(2);
        __syncthreads();
        if (c + 3 < nk) load_stage((c + 3) & 3, (c + 3) * 32);
        CP_COMMIT();

        const uint32_t sb = sbase + (c & 3) * GSTAGE;

#pragma unroll
        for (int k16 = 0; k16 < 2; ++k16) {
            const uint32_t x = k16 << 5;

            uint32_t bh[16];
#pragma unroll
            for (int nb = 0; nb < 4; ++nb)
                ldsm4(&bh[nb * 4], (sb + boff[nb]) ^ x);
#pragma unroll
            for (int mt = 0; mt < 4; ++mt) {
                uint32_t ah[4], al[4];
                ldsm4(ah, (sb + aoffH[mt]) ^ x);
                ldsm4(al, (sb + aoffL[mt]) ^ x);
#pragma unroll
                for (int nb = 0; nb < 4; ++nb) {
                    mma16816(acc[mt][2 * nb],     ah, bh[nb * 4 + 0], bh[nb * 4 + 2]);
                    mma16816(acc[mt][2 * nb],     al, bh[nb * 4 + 0], bh[nb * 4 + 2]);
                    mma16816(acc[mt][2 * nb + 1], ah, bh[nb * 4 + 1], bh[nb * 4 + 3]);
                    mma16816(acc[mt][2 * nb + 1], al, bh[nb * 4 + 1], bh[nb * 4 + 3]);
                }
            }
        }
    }

    const int gid = lid >> 2;
    const int tig = lid & 3;
#pragma unroll
    for (int mt = 0; mt < 4; ++mt) {
        int m = m0 + wm + mt * 16 + gid;
#pragma unroll
        for (int nt = 0; nt < 8; ++nt) {
            int n = n0 + wn + nt * 8 + tig * 2;
            float b0 = bias[n], b1 = bias[n + 1];
            float v00 = acc[mt][nt][0] + b0, v01 = acc[mt][nt][1] + b1;
            float v10 = acc[mt][nt][2] + b0, v11 = acc[mt][nt][3] + b1;
            if (OUTM == 0) {
                *(float2*)(C + (size_t)m * N + n)       = make_float2(v00, v01);
                *(float2*)(C + (size_t)(m + 8) * N + n) = make_float2(v10, v11);
            } else {
                uint32_t pk = pack_f16(v00, v01);
                float2 r = unpack_f16(pk);
                *(uint32_t*)(Ch + (size_t)m * N + n) = pk;
                *(uint32_t*)(Cl + (size_t)m * N + n) = pack_f16(v00 - r.x, v01 - r.y);
                pk = pack_f16(v10, v11);
                r = unpack_f16(pk);
                *(uint32_t*)(Ch + (size_t)(m + 8) * N + n) = pk;
                *(uint32_t*)(Cl + (size_t)(m + 8) * N + n) = pack_f16(v10 - r.x, v11 - r.y);
            }
        }
    }
}

// ---------------------------------------------------------------------------
// Flash attention, fp16x2 (Q split hi/lo; K,V single fp16), causal.
// CTA: 128 q-rows x 64-kv chunks. 8 warps x 16 q-rows. (unchanged from R7)
// ---------------------------------------------------------------------------
#define KV_TILE_B 16384                     // 64 rows x 256 B
#define KV_STAGE_B (2 * KV_TILE_B)          // Kh, Vh
#define Q_TILE_B   32768                    // 128 rows x 256 B
#define ATTN_SMEM (2 * Q_TILE_B + 2 * KV_STAGE_B)   // 131072

__global__ __launch_bounds__(256) void attn_mma_kernel()
{
    extern __shared__ char sm8[];
    const uint32_t sb  = smem_u32(sm8);
    const uint32_t sQh = sb, sQl = sb + Q_TILE_B;
    const uint32_t sKV = sb + 2 * Q_TILE_B;

    const int t   = threadIdx.x;
    const int wid = t >> 5;
    const int lid = t & 31;
    const int qt  = blockIdx.x;
    const int h   = blockIdx.y;
    const int b   = blockIdx.z;
    const int m0  = qt * 128;
    const int wm  = wid * 16;
    const int gid = lid >> 2;
    const int tig = lid & 3;
    const int lrow8 = (lid & 7) + ((lid >> 3) & 1) * 8;
    const int lk    = (lid >> 4) & 1;

    const size_t tok0 = ((size_t)b * Sdim + m0) * QKV_N;
    const __half* qh = g_qkvh + tok0 + h * Ddim;
    const __half* ql = g_qkvl + tok0 + h * Ddim;
    const size_t kvtok = (size_t)b * Sdim * QKV_N;
    const __half* kv_base[2] = {
        g_qkvh + kvtok + Cdim + h * Ddim,      // Kh
        g_qkvh + kvtok + 2 * Cdim + h * Ddim   // Vh
    };

    auto load_kv = [&](int stage, int n0) {
        uint32_t dstb = sKV + stage * KV_STAGE_B;
#pragma unroll
        for (int i = 0; i < 8; ++i) {
            int idx  = t + i * 256;            // 0..2047
            int tile = idx >> 10;
            int rem  = idx & 1023;
            int row  = rem >> 4, j = rem & 15;
            const void* src = kv_base[tile] + (size_t)(n0 + row) * QKV_N + j * 8;
            uint32_t dst = dstb + tile * KV_TILE_B + row * 256 + ((j ^ (row & 7)) << 4);
            CP_ASYNC16(dst, src);
        }
    };

    // Q tile loads (group 0, with chunk 0)
#pragma unroll
    for (int i = 0; i < 16; ++i) {
        int idx  = t + i * 256;                // 0..4095
        int tile = idx >> 11;                  // 0: Qh, 1: Ql
        int rem  = idx & 2047;
        int row  = rem >> 4, j = rem & 15;
        const __half* src = (tile == 0 ? qh : ql) + (size_t)row * QKV_N + j * 8;
        uint32_t dst = (tile == 0 ? sQh : sQl) + row * 256 + ((j ^ (row & 7)) << 4);
        CP_ASYNC16(dst, src);
    }
    load_kv(0, 0);
    CP_COMMIT();
    const int ktmax = (m0 >> 6) + 1;
    if (ktmax >= 1) load_kv(1, 64);
    CP_COMMIT();

    float o[16][4];
    float m_i[2] = {-1e30f, -1e30f};
    float l_i[2] = {0.f, 0.f};
#pragma unroll
    for (int nt = 0; nt < 16; ++nt)
#pragma unroll
        for (int e = 0; e < 4; ++e) o[nt][e] = 0.f;

    const float scale = 0.08838834764831845f;   // 1/sqrt(128)
    const int r0g = m0 + wm + gid;

    for (int kt = 0; kt <= ktmax; ++kt) {
        const int n0 = kt << 6;
        CP_WAIT(1);
        __syncthreads();

        const uint32_t st  = sKV + (kt & 1) * KV_STAGE_B;
        const uint32_t sKh = st, sVh = st + KV_TILE_B;

        if (m0 + wm + 15 >= n0) {
            // ---- S = (Qh+Ql) Kh^T ----
            float s[8][4];
#pragma unroll
            for (int nt = 0; nt < 8; ++nt)
#pragma unroll
                for (int e = 0; e < 4; ++e) s[nt][e] = 0.f;

#pragma unroll
            for (int ks = 0; ks < 8; ++ks) {
                const int jg = ks * 2 + lk;
                const int arow = wm + lrow8;
                uint32_t aoff = arow * 256 + ((jg ^ (arow & 7)) << 4);
                uint32_t qfh[4], qfl[4];
                ldsm4(qfh, sQh + aoff);
                ldsm4(qfl, sQl + aoff);
#pragma unroll
                for (int g = 0; g < 4; ++g) {
                    const int brow = g * 16 + lrow8;
                    uint32_t boff2 = brow * 256 + ((jg ^ (brow & 7)) << 4);
                    uint32_t kh[4];
                    ldsm4(kh, sKh + boff2);
                    mma16816(s[2 * g],     qfh, kh[0], kh[2]);
                    mma16816(s[2 * g],     qfl, kh[0], kh[2]);
                    mma16816(s[2 * g + 1], qfh, kh[1], kh[3]);
                    mma16816(s[2 * g + 1], qfl, kh[1], kh[3]);
                }
            }

            // scale + causal mask
            const bool diag = (n0 + 63 > m0 + wm);
#pragma unroll
            for (int nt = 0; nt < 8; ++nt) {
                const int c0 = n0 + nt * 8 + tig * 2;
#pragma unroll
                for (int e = 0; e < 4; ++e) s[nt][e] *= scale;
                if (diag) {
                    if (c0     > r0g)     s[nt][0] = -1e30f;
                    if (c0 + 1 > r0g)     s[nt][1] = -1e30f;
                    if (c0     > r0g + 8) s[nt][2] = -1e30f;
                    if (c0 + 1 > r0g + 8) s[nt][3] = -1e30f;
                }
            }

            // ---- online softmax ----
#pragma unroll
            for (int rr = 0; rr < 2; ++rr) {
                float mx = -1e30f;
#pragma unroll
                for (int nt = 0; nt < 8; ++nt)
                    mx = fmaxf(mx, fmaxf(s[nt][2 * rr], s[nt][2 * rr + 1]));
                mx = fmaxf(mx, __shfl_xor_sync(0xffffffffu, mx, 1));
                mx = fmaxf(mx, __shfl_xor_sync(0xffffffffu, mx, 2));
                float m_new = fmaxf(m_i[rr], mx);
                float alpha = __expf(m_i[rr] - m_new);
                float sum = 0.f;
#pragma unroll
                for (int nt = 0; nt < 8; ++nt) {
                    float p0 = __expf(s[nt][2 * rr]     - m_new);
                    float p1 = __expf(s[nt][2 * rr + 1] - m_new);
                    s[nt][2 * rr]     = p0;
                    s[nt][2 * rr + 1] = p1;
                    sum += p0 + p1;
                }
                sum += __shfl_xor_sync(0xffffffffu, sum, 1);
                sum += __shfl_xor_sync(0xffffffffu, sum, 2);
                l_i[rr] = l_i[rr] * alpha + sum;
                m_i[rr] = m_new;
#pragma unroll
                for (int nt = 0; nt < 16; ++nt) {
                    o[nt][2 * rr]     *= alpha;
                    o[nt][2 * rr + 1] *= alpha;
                }
            }

            // ---- O += (Ph+Pl) Vh ----
#pragma unroll
            for (int j = 0; j < 4; ++j) {
                uint32_t ah[4], al[4];
#pragma unroll
                for (int half = 0; half < 2; ++half) {
                    const float* sp = s[2 * j + half];
#pragma unroll
                    for (int rr = 0; rr < 2; ++rr) {
                        float p0 = sp[2 * rr], p1 = sp[2 * rr + 1];
                        uint32_t pk = pack_f16(p0, p1);
                        float2 r = unpack_f16(pk);
                        ah[half * 2 + rr] = pk;
                        al[half * 2 + rr] = pack_f16(p0 - r.x, p1 - r.y);
                    }
                }
                const int vrow = j * 16 + lrow8;
#pragma unroll
                for (int g = 0; g < 8; ++g) {
                    const int jj = g * 2 + lk;
                    uint32_t voff = vrow * 256 + ((jj ^ (vrow & 7)) << 4);
                    uint32_t vh[4];
                    ldsm4t(vh, sVh + voff);
                    mma16816(o[2 * g],     ah, vh[0], vh[1]);
                    mma16816(o[2 * g],     al, vh[0], vh[1]);
                    mma16816(o[2 * g + 1], ah, vh[2], vh[3]);
                    mma16816(o[2 * g + 1], al, vh[2], vh[3]);
                }
            }
        }

        __syncthreads();
        if (kt + 2 <= ktmax) load_kv(kt & 1, (kt + 2) << 6);
        CP_COMMIT();
    }

    // ---- epilogue: normalize, split to fp16 h/l, write ----
    const float inv0 = 1.0f / l_i[0];
    const float inv1 = 1.0f / l_i[1];
    const size_t ybase = (size_t)b * Sdim * Cdim + (size_t)h * Ddim;
    __half* yh = g_yh + ybase;
    __half* yl = g_yl + ybase;
    const size_t row0 = (size_t)(m0 + wm + gid) * Cdim;
    const size_t row1 = row0 + 8 * Cdim;
#pragma unroll
    for (int nt = 0; nt < 16; ++nt) {
        const int col = nt * 8 + tig * 2;
        float p0 = o[nt][0] * inv0, p1 = o[nt][1] * inv0;
        uint32_t pk = pack_f16(p0, p1);
        float2 r = unpack_f16(pk);
        *(uint32_t*)(yh + row0 + col) = pk;
        *(uint32_t*)(yl + row0 + col) = pack_f16(p0 - r.x, p1 - r.y);
        p0 = o[nt][2] * inv1; p1 = o[nt][3] * inv1;
        pk = pack_f16(p0, p1);
        r = unpack_f16(pk);
        *(uint32_t*)(yh + row1 + col) = pk;
        *(uint32_t*)(yl + row1 + col) = pack_f16(p0 - r.x, p1 - r.y);
    }
}

// ---------------------------------------------------------------------------
// Launch
// ---------------------------------------------------------------------------
extern "C" void kernel_launch(void* const* d_in, const int* in_sizes, int n_in,
                              void* d_out, int out_size)
{
    const float* x      = (const float*)d_in[0];
    const float* w_qkv  = (const float*)d_in[1];
    const float* b_qkv  = (const float*)d_in[2];
    const float* w_proj = (const float*)d_in[3];
    const float* b_proj = (const float*)d_in[4];
    float* out = (float*)d_out;

    __half *qkvh, *qkvl, *xh, *xl, *yh, *yl, *wq, *wp;
    cudaGetSymbolAddress((void**)&qkvh, g_qkvh);
    cudaGetSymbolAddress((void**)&qkvl, g_qkvl);
    cudaGetSymbolAddress((void**)&xh,  g_xh);
    cudaGetSymbolAddress((void**)&xl,  g_xl);
    cudaGetSymbolAddress((void**)&yh,  g_yh);
    cudaGetSymbolAddress((void**)&yl,  g_yl);
    cudaGetSymbolAddress((void**)&wq,  g_wqkvT);
    cudaGetSymbolAddress((void**)&wp,  g_wprojT);

    cudaFuncSetAttribute(gemm_mma_kernel<0>,
                         cudaFuncAttributeMaxDynamicSharedMemorySize, GEMM_SMEM);
    cudaFuncSetAttribute(gemm_mma_kernel<1>,
                         cudaFuncAttributeMaxDynamicSharedMemorySize, GEMM_SMEM);
    cudaFuncSetAttribute(attn_mma_kernel,
                         cudaFuncAttributeMaxDynamicSharedMemorySize, ATTN_SMEM);

    // 1) input splits / weight transposes (fp16)
    {
        int n = Mtok * Cdim;
        split_kernel<<<(n / 4 + 255) / 256, 256>>>(x, xh, xl, n);
    }
    transpose_h_kernel<<<dim3(QKV_N / 32, Cdim / 32), dim3(32, 8)>>>(
        w_qkv, wq, Cdim, QKV_N);
    transpose_h_kernel<<<dim3(Cdim / 32, Cdim / 32), dim3(32, 8)>>>(
        w_proj, wp, Cdim, Cdim);

    // 2) qkv = x @ w_qkv + b_qkv   [8192, 6144] -> split fp16 h/l
    gemm_mma_kernel<1><<<dim3(QKV_N / 128, Mtok / 128), 128, GEMM_SMEM>>>(
        xh, xl, wq, b_qkv, nullptr, qkvh, qkvl, Mtok, QKV_N, Cdim);

    // 3) flash attention -> yh/yl fp16
    {
        dim3 grid(Sdim / 128, Hdim, Bdim);
        attn_mma_kernel<<<grid, 256, ATTN_SMEM>>>();
    }

    // 4) out = y @ w_proj + b_proj   [8192, 2048] fp32
    gemm_mma_kernel<0><<<dim3(Cdim / 128, Mtok / 128), 128, GEMM_SMEM>>>(
        yh, yl, wp, b_proj, out, nullptr, nullptr, Mtok, Cdim, Cdim);
}

// round 9
// speedup vs baseline: 1.1190x; 1.1190x over previous
#include <cuda_runtime.h>
#include <cuda_fp16.h>
#include <cstdint>

// Problem constants
#define Cdim 2048
#define Sdim 2048
#define Bdim 4
#define Hdim 16
#define Ddim 128
#define Mtok (Bdim * Sdim)          // 8192
#define QKV_N (3 * Cdim)            // 6144

// ---------------------------------------------------------------------------
// Scratch (device globals — no allocation allowed)
// ---------------------------------------------------------------------------
__device__ __half g_qkvh[(size_t)Mtok * QKV_N];      // qkv (fp16, hi only)
__device__ __half g_xh[(size_t)Mtok * Cdim];
__device__ __half g_xl[(size_t)Mtok * Cdim];
__device__ __half g_yh[(size_t)Mtok * Cdim];
__device__ __half g_yl[(size_t)Mtok * Cdim];
__device__ __half g_wqkvT[(size_t)QKV_N * Cdim];     // [6144, 2048] (N,K) fp16
__device__ __half g_wprojT[(size_t)Cdim * Cdim];     // [2048, 2048] fp16

// ---------------------------------------------------------------------------
// PTX helpers (base-ISA only: cp.async / ldmatrix / mma.sync)
// ---------------------------------------------------------------------------
__device__ __forceinline__ uint32_t smem_u32(const void* p) {
    uint32_t a;
    asm("{ .reg .u64 t; cvta.to.shared.u64 t, %1; cvt.u32.u64 %0, t; }" : "=r"(a) : "l"(p));
    return a;
}

#define CP_ASYNC16(dst, src) \
    asm volatile("cp.async.cg.shared.global [%0], [%1], 16;" :: "r"(dst), "l"(src))
#define CP_COMMIT() asm volatile("cp.async.commit_group;" ::: "memory")
#define CP_WAIT(n)  asm volatile("cp.async.wait_group %0;" :: "n"(n) : "memory")

__device__ __forceinline__ void ldsm4(uint32_t* r, uint32_t addr) {
    asm volatile("ldmatrix.sync.aligned.m8n8.x4.shared.b16 {%0,%1,%2,%3}, [%4];"
                 : "=r"(r[0]), "=r"(r[1]), "=r"(r[2]), "=r"(r[3]) : "r"(addr));
}
__device__ __forceinline__ void ldsm4t(uint32_t* r, uint32_t addr) {
    asm volatile("ldmatrix.sync.aligned.m8n8.x4.trans.shared.b16 {%0,%1,%2,%3}, [%4];"
                 : "=r"(r[0]), "=r"(r[1]), "=r"(r[2]), "=r"(r[3]) : "r"(addr));
}

// fp16 MMA, fp32 accumulate
__device__ __forceinline__ void mma16816(float* d, const uint32_t* a,
                                         uint32_t b0, uint32_t b1) {
    asm volatile(
        "mma.sync.aligned.m16n8k16.row.col.f32.f16.f16.f32 "
        "{%0,%1,%2,%3}, {%4,%5,%6,%7}, {%8,%9}, {%0,%1,%2,%3};"
        : "+f"(d[0]), "+f"(d[1]), "+f"(d[2]), "+f"(d[3])
        : "r"(a[0]), "r"(a[1]), "r"(a[2]), "r"(a[3]), "r"(b0), "r"(b1));
}

// pack two fp32 -> fp16x2 (first arg in low half)
__device__ __forceinline__ uint32_t pack_f16(float lo, float hi) {
    uint32_t r;
    asm("cvt.rn.f16x2.f32 %0, %1, %2;" : "=r"(r) : "f"(hi), "f"(lo));
    return r;
}
__device__ __forceinline__ float2 unpack_f16(uint32_t pk) {
    __half2 h = *reinterpret_cast<__half2*>(&pk);
    return make_float2(__low2float(h), __high2float(h));
}

// ---------------------------------------------------------------------------
// Conversion kernels
// ---------------------------------------------------------------------------
__global__ void split_kernel(const float* __restrict__ in,
                             __half* __restrict__ hi,
                             __half* __restrict__ lo, int n)
{
    int i = (blockIdx.x * blockDim.x + threadIdx.x) * 4;
    if (i >= n) return;
    float4 v = *(const float4*)(in + i);
    float vv[4] = {v.x, v.y, v.z, v.w};
    uint32_t hp[2], lp[2];
#pragma unroll
    for (int p = 0; p < 2; ++p) {
        uint32_t pk = pack_f16(vv[2 * p], vv[2 * p + 1]);
        float2 r = unpack_f16(pk);
        hp[p] = pk;
        lp[p] = pack_f16(vv[2 * p] - r.x, vv[2 * p + 1] - r.y);
    }
    *(uint2*)(hi + i) = make_uint2(hp[0], hp[1]);
    *(uint2*)(lo + i) = make_uint2(lp[0], lp[1]);
}

// W [K, N] fp32 -> Wt [N, K] fp16 (single-term B side)
__global__ void transpose_h_kernel(const float* __restrict__ W,
                                   __half* __restrict__ Th, int K, int N)
{
    __shared__ float tile[32][33];
    int n0 = blockIdx.x * 32, k0 = blockIdx.y * 32;
    int tx = threadIdx.x, ty = threadIdx.y;   // 32 x 8
#pragma unroll
    for (int j = 0; j < 32; j += 8)
        tile[ty + j][tx] = W[(size_t)(k0 + ty + j) * N + n0 + tx];
    __syncthreads();
#pragma unroll
    for (int j = 0; j < 32; j += 8)
        Th[(size_t)(n0 + ty + j) * K + k0 + tx] = __float2half(tile[tx][ty + j]);
}

// ---------------------------------------------------------------------------
// fp16x2 GEMM (R7 config — best measured): C = (Ah+Al) @ Bh^T + bias.
// CTA 128x128, BK=32, 8 warps (4m x 2n) 32x64 warp tiles, 4-stage, 2 CTAs/SM.
// OUTM=0: fp32 C.  OUTM=1: fp16 Ch (hi only).
// ---------------------------------------------------------------------------
#define GA_TILE 8192                       // 128 x 32 fp16
#define GSTAGE (3 * GA_TILE)               // Ah, Al, B  = 24576
#define GEMM_SMEM (4 * GSTAGE)             // 98304

template<int OUTM>
__global__ __launch_bounds__(256, 2) void gemm_mma_kernel(
    const __half* __restrict__ Ah, const __half* __restrict__ Al,
    const __half* __restrict__ Bh,
    const float* __restrict__ bias, float* __restrict__ C,
    __half* __restrict__ Ch,
    int M, int N, int K)
{
    extern __shared__ char smem[];
    const uint32_t sbase = smem_u32(smem);

    const int t   = threadIdx.x;
    const int wid = t >> 5;
    const int lid = t & 31;
    const int n0  = blockIdx.x * 128;
    const int m0  = blockIdx.y * 128;
    const int wm  = (wid & 3) * 32;
    const int wn  = (wid >> 2) * 64;

    const __half* gA[2] = { Ah + (size_t)m0 * K, Al + (size_t)m0 * K };
    const __half* gB    = Bh + (size_t)n0 * K;

    float acc[2][8][4];
#pragma unroll
    for (int mt = 0; mt < 2; ++mt)
#pragma unroll
        for (int nt = 0; nt < 8; ++nt)
#pragma unroll
            for (int e = 0; e < 4; ++e) acc[mt][nt][e] = 0.f;

    auto load_stage = [&](int stage, int k0) {
        uint32_t sb = sbase + stage * GSTAGE;
#pragma unroll
        for (int i = 0; i < 4; ++i) {
            int idx = t + i * 256;          // < 1024
            int tl  = idx >> 9;
            int rem = idx & 511;
            int row = rem >> 2, j = rem & 3;
            const void* src = gA[tl] + (size_t)row * K + k0 + j * 8;
            uint32_t dst = sb + tl * GA_TILE + row * 64 + ((j ^ ((row >> 1) & 3)) << 4);
            CP_ASYNC16(dst, src);
        }
#pragma unroll
        for (int i = 0; i < 2; ++i) {
            int idx = t + i * 256;          // < 512
            int row = idx >> 2, j = idx & 3;
            const void* src = gB + (size_t)row * K + k0 + j * 8;
            uint32_t dst = sb + 2 * GA_TILE + row * 64 + ((j ^ ((row >> 1) & 3)) << 4);
            CP_ASYNC16(dst, src);
        }
    };

    const int lrow8 = (lid & 7) + ((lid >> 3) & 1) * 8;
    const int lk    = (lid >> 4) & 1;

    const int nk = K / 32;                  // 64 chunks
    load_stage(0, 0);  CP_COMMIT();
    load_stage(1, 32); CP_COMMIT();
    load_stage(2, 64); CP_COMMIT();

    for (int c = 0; c < nk; ++c) {
        CP_WAIT(2);
        __syncthreads();
        if (c + 3 < nk) load_stage((c + 3) & 3, (c + 3) * 32);
        CP_COMMIT();

        const uint32_t sb = sbase + (c & 3) * GSTAGE;
        const uint32_t aH = sb, aL = sb + GA_TILE, bH = sb + 2 * GA_TILE;

#pragma unroll
        for (int k16 = 0; k16 < 2; ++k16) {
            const int jg = k16 * 2 + lk;

            uint32_t bh[16];
#pragma unroll
            for (int nb = 0; nb < 4; ++nb) {
                int row = wn + nb * 16 + lrow8;
                uint32_t off = row * 64 + ((jg ^ ((row >> 1) & 3)) << 4);
                ldsm4(&bh[nb * 4], bH + off);
            }
#pragma unroll
            for (int mt = 0; mt < 2; ++mt) {
                int row = wm + mt * 16 + lrow8;
                uint32_t off = row * 64 + ((jg ^ ((row >> 1) & 3)) << 4);
                uint32_t ah[4], al[4];
                ldsm4(ah, aH + off);
                ldsm4(al, aL + off);
#pragma unroll
                for (int nb = 0; nb < 4; ++nb) {
                    mma16816(acc[mt][2 * nb],     ah, bh[nb * 4 + 0], bh[nb * 4 + 2]);
                    mma16816(acc[mt][2 * nb],     al, bh[nb * 4 + 0], bh[nb * 4 + 2]);
                    mma16816(acc[mt][2 * nb + 1], ah, bh[nb * 4 + 1], bh[nb * 4 + 3]);
                    mma16816(acc[mt][2 * nb + 1], al, bh[nb * 4 + 1], bh[nb * 4 + 3]);
                }
            }
        }
    }

    const int gid = lid >> 2;
    const int tig = lid & 3;
#pragma unroll
    for (int mt = 0; mt < 2; ++mt) {
        int m = m0 + wm + mt * 16 + gid;
#pragma unroll
        for (int nt = 0; nt < 8; ++nt) {
            int n = n0 + wn + nt * 8 + tig * 2;
            float b0 = bias[n], b1 = bias[n + 1];
            float v00 = acc[mt][nt][0] + b0, v01 = acc[mt][nt][1] + b1;
            float v10 = acc[mt][nt][2] + b0, v11 = acc[mt][nt][3] + b1;
            if (OUTM == 0) {
                *(float2*)(C + (size_t)m * N + n)       = make_float2(v00, v01);
                *(float2*)(C + (size_t)(m + 8) * N + n) = make_float2(v10, v11);
            } else {
                *(uint32_t*)(Ch + (size_t)m * N + n)       = pack_f16(v00, v01);
                *(uint32_t*)(Ch + (size_t)(m + 8) * N + n) = pack_f16(v10, v11);
            }
        }
    }
}

// ---------------------------------------------------------------------------
// Flash attention, pure fp16 MMA operands (Q, K, V, P single-term), causal.
// CTA: 128 q-rows x 64-kv chunks. 8 warps x 16 q-rows. 3-stage KV pipeline.
// Smem: Q (32 KB) + 3 x {K,V} (3 x 32 KB) = 128 KB.
// Epilogue still writes yh/yl fp16 h/l (proj GEMM stays 2-pass).
// ---------------------------------------------------------------------------
#define KV_TILE_B 16384                     // 64 rows x 256 B
#define KV_STAGE_B (2 * KV_TILE_B)          // Kh, Vh
#define Q_TILE_B   32768                    // 128 rows x 256 B
#define ATTN_SMEM (Q_TILE_B + 3 * KV_STAGE_B)   // 131072

__global__ __launch_bounds__(256) void attn_mma_kernel()
{
    extern __shared__ char sm8[];
    const uint32_t sb  = smem_u32(sm8);
    const uint32_t sQh = sb;
    const uint32_t sKV = sb + Q_TILE_B;

    const int t   = threadIdx.x;
    const int wid = t >> 5;
    const int lid = t & 31;
    const int qt  = blockIdx.x;
    const int h   = blockIdx.y;
    const int b   = blockIdx.z;
    const int m0  = qt * 128;
    const int wm  = wid * 16;
    const int gid = lid >> 2;
    const int tig = lid & 3;
    const int lrow8 = (lid & 7) + ((lid >> 3) & 1) * 8;
    const int lk    = (lid >> 4) & 1;

    const size_t tok0 = ((size_t)b * Sdim + m0) * QKV_N;
    const __half* qh = g_qkvh + tok0 + h * Ddim;
    const size_t kvtok = (size_t)b * Sdim * QKV_N;
    const __half* kv_base[2] = {
        g_qkvh + kvtok + Cdim + h * Ddim,      // K
        g_qkvh + kvtok + 2 * Cdim + h * Ddim   // V
    };

    auto load_kv = [&](int stage, int n0) {
        uint32_t dstb = sKV + stage * KV_STAGE_B;
#pragma unroll
        for (int i = 0; i < 8; ++i) {
            int idx  = t + i * 256;            // 0..2047
            int tile = idx >> 10;
            int rem  = idx & 1023;
            int row  = rem >> 4, j = rem & 15;
            const void* src = kv_base[tile] + (size_t)(n0 + row) * QKV_N + j * 8;
            uint32_t dst = dstb + tile * KV_TILE_B + row * 256 + ((j ^ (row & 7)) << 4);
            CP_ASYNC16(dst, src);
        }
    };

    const int ktmax = (m0 >> 6) + 1;

    // Q tile loads (group 0, with kv chunk 0)
#pragma unroll
    for (int i = 0; i < 8; ++i) {
        int idx  = t + i * 256;                // 0..2047
        int row  = idx >> 4, j = idx & 15;
        const __half* src = qh + (size_t)row * QKV_N + j * 8;
        uint32_t dst = sQh + row * 256 + ((j ^ (row & 7)) << 4);
        CP_ASYNC16(dst, src);
    }
    load_kv(0, 0);
    CP_COMMIT();                               // g0: Q + kv0
    if (ktmax >= 1) load_kv(1, 64);
    CP_COMMIT();                               // g1
    if (ktmax >= 2) load_kv(2, 128);
    CP_COMMIT();                               // g2

    float o[16][4];
    float m_i[2] = {-1e30f, -1e30f};
    float l_i[2] = {0.f, 0.f};
#pragma unroll
    for (int nt = 0; nt < 16; ++nt)
#pragma unroll
        for (int e = 0; e < 4; ++e) o[nt][e] = 0.f;

    const float scale = 0.08838834764831845f;   // 1/sqrt(128)
    const int r0g = m0 + wm + gid;

    for (int kt = 0; kt <= ktmax; ++kt) {
        const int n0 = kt << 6;
        CP_WAIT(2);                 // chunk kt resident
        __syncthreads();

        const uint32_t st  = sKV + (kt % 3) * KV_STAGE_B;
        const uint32_t sKh = st, sVh = st + KV_TILE_B;

        if (m0 + wm + 15 >= n0) {
            // ---- S = Q K^T (fp16 single pass) ----
            float s[8][4];
#pragma unroll
            for (int nt = 0; nt < 8; ++nt)
#pragma unroll
                for (int e = 0; e < 4; ++e) s[nt][e] = 0.f;

#pragma unroll
            for (int ks = 0; ks < 8; ++ks) {
                const int jg = ks * 2 + lk;
                const int arow = wm + lrow8;
                uint32_t aoff = arow * 256 + ((jg ^ (arow & 7)) << 4);
                uint32_t qf[4];
                ldsm4(qf, sQh + aoff);
#pragma unroll
                for (int g = 0; g < 4; ++g) {
                    const int brow = g * 16 + lrow8;
                    uint32_t boff = brow * 256 + ((jg ^ (brow & 7)) << 4);
                    uint32_t kh[4];
                    ldsm4(kh, sKh + boff);
                    mma16816(s[2 * g],     qf, kh[0], kh[2]);
                    mma16816(s[2 * g + 1], qf, kh[1], kh[3]);
                }
            }

            // scale + causal mask
            const bool diag = (n0 + 63 > m0 + wm);
#pragma unroll
            for (int nt = 0; nt < 8; ++nt) {
                const int c0 = n0 + nt * 8 + tig * 2;
#pragma unroll
                for (int e = 0; e < 4; ++e) s[nt][e] *= scale;
                if (diag) {
                    if (c0     > r0g)     s[nt][0] = -1e30f;
                    if (c0 + 1 > r0g)     s[nt][1] = -1e30f;
                    if (c0     > r0g + 8) s[nt][2] = -1e30f;
                    if (c0 + 1 > r0g + 8) s[nt][3] = -1e30f;
                }
            }

            // ---- online softmax ----
#pragma unroll
            for (int rr = 0; rr < 2; ++rr) {
                float mx = -1e30f;
#pragma unroll
                for (int nt = 0; nt < 8; ++nt)
                    mx = fmaxf(mx, fmaxf(s[nt][2 * rr], s[nt][2 * rr + 1]));
                mx = fmaxf(mx, __shfl_xor_sync(0xffffffffu, mx, 1));
                mx = fmaxf(mx, __shfl_xor_sync(0xffffffffu, mx, 2));
                float m_new = fmaxf(m_i[rr], mx);
                float alpha = __expf(m_i[rr] - m_new);
                float sum = 0.f;
#pragma unroll
                for (int nt = 0; nt < 8; ++nt) {
                    float p0 = __expf(s[nt][2 * rr]     - m_new);
                    float p1 = __expf(s[nt][2 * rr + 1] - m_new);
                    s[nt][2 * rr]     = p0;
                    s[nt][2 * rr + 1] = p1;
                    sum += p0 + p1;
                }
                sum += __shfl_xor_sync(0xffffffffu, sum, 1);
                sum += __shfl_xor_sync(0xffffffffu, sum, 2);
                l_i[rr] = l_i[rr] * alpha + sum;
                m_i[rr] = m_new;
#pragma unroll
                for (int nt = 0; nt < 16; ++nt) {
                    o[nt][2 * rr]     *= alpha;
                    o[nt][2 * rr + 1] *= alpha;
                }
            }

            // ---- O += P V (fp16 single pass) ----
#pragma unroll
            for (int j = 0; j < 4; ++j) {
                uint32_t ap[4];
#pragma unroll
                for (int half = 0; half < 2; ++half) {
                    const float* sp = s[2 * j + half];
                    ap[half * 2 + 0] = pack_f16(sp[0], sp[1]);
                    ap[half * 2 + 1] = pack_f16(sp[2], sp[3]);
                }
                const int vrow = j * 16 + lrow8;
#pragma unroll
                for (int g = 0; g < 8; ++g) {
                    const int jj = g * 2 + lk;
                    uint32_t voff = vrow * 256 + ((jj ^ (vrow & 7)) << 4);
                    uint32_t vh[4];
                    ldsm4t(vh, sVh + voff);
                    mma16816(o[2 * g],     ap, vh[0], vh[1]);
                    mma16816(o[2 * g + 1], ap, vh[2], vh[3]);
                }
            }
        }

        __syncthreads();            // all warps done reading stage kt%3
        if (kt + 3 <= ktmax) load_kv((kt) % 3, (kt + 3) << 6);
        CP_COMMIT();                // always commit (possibly empty)
    }

    // ---- epilogue: normalize, split to fp16 h/l, write (proj is 2-pass) ----
    const float inv0 = 1.0f / l_i[0];
    const float inv1 = 1.0f / l_i[1];
    const size_t ybase = (size_t)b * Sdim * Cdim + (size_t)h * Ddim;
    __half* yh = g_yh + ybase;
    __half* yl = g_yl + ybase;
    const size_t row0 = (size_t)(m0 + wm + gid) * Cdim;
    const size_t row1 = row0 + 8 * Cdim;
#pragma unroll
    for (int nt = 0; nt < 16; ++nt) {
        const int col = nt * 8 + tig * 2;
        float p0 = o[nt][0] * inv0, p1 = o[nt][1] * inv0;
        uint32_t pk = pack_f16(p0, p1);
        float2 r = unpack_f16(pk);
        *(uint32_t*)(yh + row0 + col) = pk;
        *(uint32_t*)(yl + row0 + col) = pack_f16(p0 - r.x, p1 - r.y);
        p0 = o[nt][2] * inv1; p1 = o[nt][3] * inv1;
        pk = pack_f16(p0, p1);
        r = unpack_f16(pk);
        *(uint32_t*)(yh + row1 + col) = pk;
        *(uint32_t*)(yl + row1 + col) = pack_f16(p0 - r.x, p1 - r.y);
    }
}

// ---------------------------------------------------------------------------
// Launch
// ---------------------------------------------------------------------------
extern "C" void kernel_launch(void* const* d_in, const int* in_sizes, int n_in,
                              void* d_out, int out_size)
{
    const float* x      = (const float*)d_in[0];
    const float* w_qkv  = (const float*)d_in[1];
    const float* b_qkv  = (const float*)d_in[2];
    const float* w_proj = (const float*)d_in[3];
    const float* b_proj = (const float*)d_in[4];
    float* out = (float*)d_out;

    __half *qkvh, *xh, *xl, *yh, *yl, *wq, *wp;
    cudaGetSymbolAddress((void**)&qkvh, g_qkvh);
    cudaGetSymbolAddress((void**)&xh,  g_xh);
    cudaGetSymbolAddress((void**)&xl,  g_xl);
    cudaGetSymbolAddress((void**)&yh,  g_yh);
    cudaGetSymbolAddress((void**)&yl,  g_yl);
    cudaGetSymbolAddress((void**)&wq,  g_wqkvT);
    cudaGetSymbolAddress((void**)&wp,  g_wprojT);

    cudaFuncSetAttribute(gemm_mma_kernel<0>,
                         cudaFuncAttributeMaxDynamicSharedMemorySize, GEMM_SMEM);
    cudaFuncSetAttribute(gemm_mma_kernel<1>,
                         cudaFuncAttributeMaxDynamicSharedMemorySize, GEMM_SMEM);
    cudaFuncSetAttribute(attn_mma_kernel,
                         cudaFuncAttributeMaxDynamicSharedMemorySize, ATTN_SMEM);

    // 1) input splits / weight transposes (fp16)
    {
        int n = Mtok * Cdim;
        split_kernel<<<(n / 4 + 255) / 256, 256>>>(x, xh, xl, n);
    }
    transpose_h_kernel<<<dim3(QKV_N / 32, Cdim / 32), dim3(32, 8)>>>(
        w_qkv, wq, Cdim, QKV_N);
    transpose_h_kernel<<<dim3(Cdim / 32, Cdim / 32), dim3(32, 8)>>>(
        w_proj, wp, Cdim, Cdim);

    // 2) qkv = x @ w_qkv + b_qkv   [8192, 6144] -> fp16 (hi only)
    gemm_mma_kernel<1><<<dim3(QKV_N / 128, Mtok / 128), 256, GEMM_SMEM>>>(
        xh, xl, wq, b_qkv, nullptr, qkvh, Mtok, QKV_N, Cdim);

    // 3) flash attention (pure fp16 operands) -> yh/yl fp16
    {
        dim3 grid(Sdim / 128, Hdim, Bdim);
        attn_mma_kernel<<<grid, 256, ATTN_SMEM>>>();
    }

    // 4) out = y @ w_proj + b_proj   [8192, 2048] fp32
    gemm_mma_kernel<0><<<dim3(Cdim / 128, Mtok / 128), 256, GEMM_SMEM>>>(
        yh, yl, wp, b_proj, out, nullptr, Mtok, Cdim, Cdim);
}

// round 10
// speedup vs baseline: 1.8962x; 1.6945x over previous
#include <cuda_runtime.h>
#include <cuda_fp16.h>
#include <cstdint>

// Problem constants
#define Cdim 2048
#define Sdim 2048
#define Bdim 4
#define Hdim 16
#define Ddim 128
#define Mtok (Bdim * Sdim)          // 8192
#define QKV_N (3 * Cdim)            // 6144

// ---------------------------------------------------------------------------
// Scratch (device globals — no allocation allowed)
// ---------------------------------------------------------------------------
__device__ __half g_qkvh[(size_t)Mtok * QKV_N];      // qkv (fp16)
__device__ __half g_xh[(size_t)Mtok * Cdim];         // x   (fp16)
__device__ __half g_yh[(size_t)Mtok * Cdim];         // y   (fp16)
__device__ __half g_wqkvT[(size_t)QKV_N * Cdim];     // [6144, 2048] (N,K) fp16
__device__ __half g_wprojT[(size_t)Cdim * Cdim];     // [2048, 2048] fp16

// ---------------------------------------------------------------------------
// PTX helpers (base-ISA only: cp.async / ldmatrix / mma.sync)
// ---------------------------------------------------------------------------
__device__ __forceinline__ uint32_t smem_u32(const void* p) {
    uint32_t a;
    asm("{ .reg .u64 t; cvta.to.shared.u64 t, %1; cvt.u32.u64 %0, t; }" : "=r"(a) : "l"(p));
    return a;
}

#define CP_ASYNC16(dst, src) \
    asm volatile("cp.async.cg.shared.global [%0], [%1], 16;" :: "r"(dst), "l"(src))
#define CP_COMMIT() asm volatile("cp.async.commit_group;" ::: "memory")
#define CP_WAIT(n)  asm volatile("cp.async.wait_group %0;" :: "n"(n) : "memory")

__device__ __forceinline__ void ldsm4(uint32_t* r, uint32_t addr) {
    asm volatile("ldmatrix.sync.aligned.m8n8.x4.shared.b16 {%0,%1,%2,%3}, [%4];"
                 : "=r"(r[0]), "=r"(r[1]), "=r"(r[2]), "=r"(r[3]) : "r"(addr));
}
__device__ __forceinline__ void ldsm4t(uint32_t* r, uint32_t addr) {
    asm volatile("ldmatrix.sync.aligned.m8n8.x4.trans.shared.b16 {%0,%1,%2,%3}, [%4];"
                 : "=r"(r[0]), "=r"(r[1]), "=r"(r[2]), "=r"(r[3]) : "r"(addr));
}

// fp16 MMA, fp32 accumulate
__device__ __forceinline__ void mma16816(float* d, const uint32_t* a,
                                         uint32_t b0, uint32_t b1) {
    asm volatile(
        "mma.sync.aligned.m16n8k16.row.col.f32.f16.f16.f32 "
        "{%0,%1,%2,%3}, {%4,%5,%6,%7}, {%8,%9}, {%0,%1,%2,%3};"
        : "+f"(d[0]), "+f"(d[1]), "+f"(d[2]), "+f"(d[3])
        : "r"(a[0]), "r"(a[1]), "r"(a[2]), "r"(a[3]), "r"(b0), "r"(b1));
}

// pack two fp32 -> fp16x2 (first arg in low half)
__device__ __forceinline__ uint32_t pack_f16(float lo, float hi) {
    uint32_t r;
    asm("cvt.rn.f16x2.f32 %0, %1, %2;" : "=r"(r) : "f"(hi), "f"(lo));
    return r;
}

// ---------------------------------------------------------------------------
// Conversion kernels (fp32 -> fp16, single term)
// ---------------------------------------------------------------------------
__global__ void convert_h_kernel(const float* __restrict__ in,
                                 __half* __restrict__ hi, int n)
{
    int i = (blockIdx.x * blockDim.x + threadIdx.x) * 4;
    if (i >= n) return;
    float4 v = *(const float4*)(in + i);
    *(uint2*)(hi + i) = make_uint2(pack_f16(v.x, v.y), pack_f16(v.z, v.w));
}

// W [K, N] fp32 -> Wt [N, K] fp16
__global__ void transpose_h_kernel(const float* __restrict__ W,
                                   __half* __restrict__ Th, int K, int N)
{
    __shared__ float tile[32][33];
    int n0 = blockIdx.x * 32, k0 = blockIdx.y * 32;
    int tx = threadIdx.x, ty = threadIdx.y;   // 32 x 8
#pragma unroll
    for (int j = 0; j < 32; j += 8)
        tile[ty + j][tx] = W[(size_t)(k0 + ty + j) * N + n0 + tx];
    __syncthreads();
#pragma unroll
    for (int j = 0; j < 32; j += 8)
        Th[(size_t)(n0 + ty + j) * K + k0 + tx] = __float2half(tile[tx][ty + j]);
}

// ---------------------------------------------------------------------------
// fp16 single-pass GEMM: C[M,N] = A @ B^T + bias. CTA 128x128, BK=32,
// 8 warps (4m x 2n) 32x64 warp tiles, 4-stage cp.async, 2 CTAs/SM.
// OUTM=0: fp32 C.  OUTM=1: fp16 Ch.
// ---------------------------------------------------------------------------
#define GA_TILE 8192                       // 128 x 32 fp16
#define GSTAGE (2 * GA_TILE)               // A, B = 16384
#define GEMM_SMEM (4 * GSTAGE)             // 65536

template<int OUTM>
__global__ __launch_bounds__(256, 2) void gemm_mma_kernel(
    const __half* __restrict__ Ah,
    const __half* __restrict__ Bh,
    const float* __restrict__ bias, float* __restrict__ C,
    __half* __restrict__ Ch,
    int M, int N, int K)
{
    extern __shared__ char smem[];
    const uint32_t sbase = smem_u32(smem);

    const int t   = threadIdx.x;
    const int wid = t >> 5;
    const int lid = t & 31;
    const int n0  = blockIdx.x * 128;
    const int m0  = blockIdx.y * 128;
    const int wm  = (wid & 3) * 32;
    const int wn  = (wid >> 2) * 64;

    const __half* gA = Ah + (size_t)m0 * K;
    const __half* gB = Bh + (size_t)n0 * K;

    float acc[2][8][4];
#pragma unroll
    for (int mt = 0; mt < 2; ++mt)
#pragma unroll
        for (int nt = 0; nt < 8; ++nt)
#pragma unroll
            for (int e = 0; e < 4; ++e) acc[mt][nt][e] = 0.f;

    auto load_stage = [&](int stage, int k0) {
        uint32_t sb = sbase + stage * GSTAGE;
        // A: 512 segments, B: 512 segments
#pragma unroll
        for (int i = 0; i < 2; ++i) {
            int idx = t + i * 256;          // < 512
            int row = idx >> 2, j = idx & 3;
            const void* srcA = gA + (size_t)row * K + k0 + j * 8;
            uint32_t dst = sb + row * 64 + ((j ^ ((row >> 1) & 3)) << 4);
            CP_ASYNC16(dst, srcA);
            const void* srcB = gB + (size_t)row * K + k0 + j * 8;
            CP_ASYNC16(dst + GA_TILE, srcB);
        }
    };

    const int lrow8 = (lid & 7) + ((lid >> 3) & 1) * 8;
    const int lk    = (lid >> 4) & 1;

    const int nk = K / 32;                  // 64 chunks
    load_stage(0, 0);  CP_COMMIT();
    load_stage(1, 32); CP_COMMIT();
    load_stage(2, 64); CP_COMMIT();

    for (int c = 0; c < nk; ++c) {
        CP_WAIT(2);
        __syncthreads();
        if (c + 3 < nk) load_stage((c + 3) & 3, (c + 3) * 32);
        CP_COMMIT();

        const uint32_t sb = sbase + (c & 3) * GSTAGE;
        const uint32_t aH = sb, bH = sb + GA_TILE;

#pragma unroll
        for (int k16 = 0; k16 < 2; ++k16) {
            const int jg = k16 * 2 + lk;

            uint32_t bh[16];
#pragma unroll
            for (int nb = 0; nb < 4; ++nb) {
                int row = wn + nb * 16 + lrow8;
                uint32_t off = row * 64 + ((jg ^ ((row >> 1) & 3)) << 4);
                ldsm4(&bh[nb * 4], bH + off);
            }
#pragma unroll
            for (int mt = 0; mt < 2; ++mt) {
                int row = wm + mt * 16 + lrow8;
                uint32_t off = row * 64 + ((jg ^ ((row >> 1) & 3)) << 4);
                uint32_t ah[4];
                ldsm4(ah, aH + off);
#pragma unroll
                for (int nb = 0; nb < 4; ++nb) {
                    mma16816(acc[mt][2 * nb],     ah, bh[nb * 4 + 0], bh[nb * 4 + 2]);
                    mma16816(acc[mt][2 * nb + 1], ah, bh[nb * 4 + 1], bh[nb * 4 + 3]);
                }
            }
        }
    }

    const int gid = lid >> 2;
    const int tig = lid & 3;
#pragma unroll
    for (int mt = 0; mt < 2; ++mt) {
        int m = m0 + wm + mt * 16 + gid;
#pragma unroll
        for (int nt = 0; nt < 8; ++nt) {
            int n = n0 + wn + nt * 8 + tig * 2;
            float b0 = bias[n], b1 = bias[n + 1];
            float v00 = acc[mt][nt][0] + b0, v01 = acc[mt][nt][1] + b1;
            float v10 = acc[mt][nt][2] + b0, v11 = acc[mt][nt][3] + b1;
            if (OUTM == 0) {
                *(float2*)(C + (size_t)m * N + n)       = make_float2(v00, v01);
                *(float2*)(C + (size_t)(m + 8) * N + n) = make_float2(v10, v11);
            } else {
                *(uint32_t*)(Ch + (size_t)m * N + n)       = pack_f16(v00, v01);
                *(uint32_t*)(Ch + (size_t)(m + 8) * N + n) = pack_f16(v10, v11);
            }
        }
    }
}

// ---------------------------------------------------------------------------
// Flash attention, pure fp16 MMA operands, causal. (R9 config, hi-only output)
// CTA: 128 q-rows x 64-kv chunks. 8 warps x 16 q-rows. 3-stage KV pipeline.
// ---------------------------------------------------------------------------
#define KV_TILE_B 16384                     // 64 rows x 256 B
#define KV_STAGE_B (2 * KV_TILE_B)          // K, V
#define Q_TILE_B   32768                    // 128 rows x 256 B
#define ATTN_SMEM (Q_TILE_B + 3 * KV_STAGE_B)   // 131072

__global__ __launch_bounds__(256) void attn_mma_kernel()
{
    extern __shared__ char sm8[];
    const uint32_t sb  = smem_u32(sm8);
    const uint32_t sQh = sb;
    const uint32_t sKV = sb + Q_TILE_B;

    const int t   = threadIdx.x;
    const int wid = t >> 5;
    const int lid = t & 31;
    const int qt  = blockIdx.x;
    const int h   = blockIdx.y;
    const int b   = blockIdx.z;
    const int m0  = qt * 128;
    const int wm  = wid * 16;
    const int gid = lid >> 2;
    const int tig = lid & 3;
    const int lrow8 = (lid & 7) + ((lid >> 3) & 1) * 8;
    const int lk    = (lid >> 4) & 1;

    const size_t tok0 = ((size_t)b * Sdim + m0) * QKV_N;
    const __half* qh = g_qkvh + tok0 + h * Ddim;
    const size_t kvtok = (size_t)b * Sdim * QKV_N;
    const __half* kv_base[2] = {
        g_qkvh + kvtok + Cdim + h * Ddim,      // K
        g_qkvh + kvtok + 2 * Cdim + h * Ddim   // V
    };

    auto load_kv = [&](int stage, int n0) {
        uint32_t dstb = sKV + stage * KV_STAGE_B;
#pragma unroll
        for (int i = 0; i < 8; ++i) {
            int idx  = t + i * 256;            // 0..2047
            int tile = idx >> 10;
            int rem  = idx & 1023;
            int row  = rem >> 4, j = rem & 15;
            const void* src = kv_base[tile] + (size_t)(n0 + row) * QKV_N + j * 8;
            uint32_t dst = dstb + tile * KV_TILE_B + row * 256 + ((j ^ (row & 7)) << 4);
            CP_ASYNC16(dst, src);
        }
    };

    const int ktmax = (m0 >> 6) + 1;

    // Q tile loads (group 0, with kv chunk 0)
#pragma unroll
    for (int i = 0; i < 8; ++i) {
        int idx  = t + i * 256;                // 0..2047
        int row  = idx >> 4, j = idx & 15;
        const __half* src = qh + (size_t)row * QKV_N + j * 8;
        uint32_t dst = sQh + row * 256 + ((j ^ (row & 7)) << 4);
        CP_ASYNC16(dst, src);
    }
    load_kv(0, 0);
    CP_COMMIT();                               // g0: Q + kv0
    if (ktmax >= 1) load_kv(1, 64);
    CP_COMMIT();
    if (ktmax >= 2) load_kv(2, 128);
    CP_COMMIT();

    float o[16][4];
    float m_i[2] = {-1e30f, -1e30f};
    float l_i[2] = {0.f, 0.f};
#pragma unroll
    for (int nt = 0; nt < 16; ++nt)
#pragma unroll
        for (int e = 0; e < 4; ++e) o[nt][e] = 0.f;

    const float scale = 0.08838834764831845f;   // 1/sqrt(128)
    const int r0g = m0 + wm + gid;

    for (int kt = 0; kt <= ktmax; ++kt) {
        const int n0 = kt << 6;
        CP_WAIT(2);
        __syncthreads();

        const uint32_t st  = sKV + (kt % 3) * KV_STAGE_B;
        const uint32_t sKh = st, sVh = st + KV_TILE_B;

        if (m0 + wm + 15 >= n0) {
            // ---- S = Q K^T ----
            float s[8][4];
#pragma unroll
            for (int nt = 0; nt < 8; ++nt)
#pragma unroll
                for (int e = 0; e < 4; ++e) s[nt][e] = 0.f;

#pragma unroll
            for (int ks = 0; ks < 8; ++ks) {
                const int jg = ks * 2 + lk;
                const int arow = wm + lrow8;
                uint32_t aoff = arow * 256 + ((jg ^ (arow & 7)) << 4);
                uint32_t qf[4];
                ldsm4(qf, sQh + aoff);
#pragma unroll
                for (int g = 0; g < 4; ++g) {
                    const int brow = g * 16 + lrow8;
                    uint32_t boff = brow * 256 + ((jg ^ (brow & 7)) << 4);
                    uint32_t kh[4];
                    ldsm4(kh, sKh + boff);
                    mma16816(s[2 * g],     qf, kh[0], kh[2]);
                    mma16816(s[2 * g + 1], qf, kh[1], kh[3]);
                }
            }

            // scale + causal mask
            const bool diag = (n0 + 63 > m0 + wm);
#pragma unroll
            for (int nt = 0; nt < 8; ++nt) {
                const int c0 = n0 + nt * 8 + tig * 2;
#pragma unroll
                for (int e = 0; e < 4; ++e) s[nt][e] *= scale;
                if (diag) {
                    if (c0     > r0g)     s[nt][0] = -1e30f;
                    if (c0 + 1 > r0g)     s[nt][1] = -1e30f;
                    if (c0     > r0g + 8) s[nt][2] = -1e30f;
                    if (c0 + 1 > r0g + 8) s[nt][3] = -1e30f;
                }
            }

            // ---- online softmax ----
#pragma unroll
            for (int rr = 0; rr < 2; ++rr) {
                float mx = -1e30f;
#pragma unroll
                for (int nt = 0; nt < 8; ++nt)
                    mx = fmaxf(mx, fmaxf(s[nt][2 * rr], s[nt][2 * rr + 1]));
                mx = fmaxf(mx, __shfl_xor_sync(0xffffffffu, mx, 1));
                mx = fmaxf(mx, __shfl_xor_sync(0xffffffffu, mx, 2));
                float m_new = fmaxf(m_i[rr], mx);
                float alpha = __expf(m_i[rr] - m_new);
                float sum = 0.f;
#pragma unroll
                for (int nt = 0; nt < 8; ++nt) {
                    float p0 = __expf(s[nt][2 * rr]     - m_new);
                    float p1 = __expf(s[nt][2 * rr + 1] - m_new);
                    s[nt][2 * rr]     = p0;
                    s[nt][2 * rr + 1] = p1;
                    sum += p0 + p1;
                }
                sum += __shfl_xor_sync(0xffffffffu, sum, 1);
                sum += __shfl_xor_sync(0xffffffffu, sum, 2);
                l_i[rr] = l_i[rr] * alpha + sum;
                m_i[rr] = m_new;
#pragma unroll
                for (int nt = 0; nt < 16; ++nt) {
                    o[nt][2 * rr]     *= alpha;
                    o[nt][2 * rr + 1] *= alpha;
                }
            }

            // ---- O += P V ----
#pragma unroll
            for (int j = 0; j < 4; ++j) {
                uint32_t ap[4];
#pragma unroll
                for (int half = 0; half < 2; ++half) {
                    const float* sp = s[2 * j + half];
                    ap[half * 2 + 0] = pack_f16(sp[0], sp[1]);
                    ap[half * 2 + 1] = pack_f16(sp[2], sp[3]);
                }
                const int vrow = j * 16 + lrow8;
#pragma unroll
                for (int g = 0; g < 8; ++g) {
                    const int jj = g * 2 + lk;
                    uint32_t voff = vrow * 256 + ((jj ^ (vrow & 7)) << 4);
                    uint32_t vh[4];
                    ldsm4t(vh, sVh + voff);
                    mma16816(o[2 * g],     ap, vh[0], vh[1]);
                    mma16816(o[2 * g + 1], ap, vh[2], vh[3]);
                }
            }
        }

        __syncthreads();
        if (kt + 3 <= ktmax) load_kv(kt % 3, (kt + 3) << 6);
        CP_COMMIT();
    }

    // ---- epilogue: normalize, write fp16 y ----
    const float inv0 = 1.0f / l_i[0];
    const float inv1 = 1.0f / l_i[1];
    const size_t ybase = (size_t)b * Sdim * Cdim + (size_t)h * Ddim;
    __half* yh = g_yh + ybase;
    const size_t row0 = (size_t)(m0 + wm + gid) * Cdim;
    const size_t row1 = row0 + 8 * Cdim;
#pragma unroll
    for (int nt = 0; nt < 16; ++nt) {
        const int col = nt * 8 + tig * 2;
        *(uint32_t*)(yh + row0 + col) = pack_f16(o[nt][0] * inv0, o[nt][1] * inv0);
        *(uint32_t*)(yh + row1 + col) = pack_f16(o[nt][2] * inv1, o[nt][3] * inv1);
    }
}

// ---------------------------------------------------------------------------
// Launch
// ---------------------------------------------------------------------------
extern "C" void kernel_launch(void* const* d_in, const int* in_sizes, int n_in,
                              void* d_out, int out_size)
{
    const float* x      = (const float*)d_in[0];
    const float* w_qkv  = (const float*)d_in[1];
    const float* b_qkv  = (const float*)d_in[2];
    const float* w_proj = (const float*)d_in[3];
    const float* b_proj = (const float*)d_in[4];
    float* out = (float*)d_out;

    __half *qkvh, *xh, *yh, *wq, *wp;
    cudaGetSymbolAddress((void**)&qkvh, g_qkvh);
    cudaGetSymbolAddress((void**)&xh,  g_xh);
    cudaGetSymbolAddress((void**)&yh,  g_yh);
    cudaGetSymbolAddress((void**)&wq,  g_wqkvT);
    cudaGetSymbolAddress((void**)&wp,  g_wprojT);

    cudaFuncSetAttribute(gemm_mma_kernel<0>,
                         cudaFuncAttributeMaxDynamicSharedMemorySize, GEMM_SMEM);
    cudaFuncSetAttribute(gemm_mma_kernel<1>,
                         cudaFuncAttributeMaxDynamicSharedMemorySize, GEMM_SMEM);
    cudaFuncSetAttribute(attn_mma_kernel,
                         cudaFuncAttributeMaxDynamicSharedMemorySize, ATTN_SMEM);

    // 1) input convert / weight transposes (fp16)
    {
        int n = Mtok * Cdim;
        convert_h_kernel<<<(n / 4 + 255) / 256, 256>>>(x, xh, n);
    }
    transpose_h_kernel<<<dim3(QKV_N / 32, Cdim / 32), dim3(32, 8)>>>(
        w_qkv, wq, Cdim, QKV_N);
    transpose_h_kernel<<<dim3(Cdim / 32, Cdim / 32), dim3(32, 8)>>>(
        w_proj, wp, Cdim, Cdim);

    // 2) qkv = x @ w_qkv + b_qkv   [8192, 6144] -> fp16
    gemm_mma_kernel<1><<<dim3(QKV_N / 128, Mtok / 128), 256, GEMM_SMEM>>>(
        xh, wq, b_qkv, nullptr, qkvh, Mtok, QKV_N, Cdim);

    // 3) flash attention (fp16) -> yh
    {
        dim3 grid(Sdim / 128, Hdim, Bdim);
        attn_mma_kernel<<<grid, 256, ATTN_SMEM>>>();
    }

    // 4) out = y @ w_proj + b_proj   [8192, 2048] fp32
    gemm_mma_kernel<0><<<dim3(Cdim / 128, Mtok / 128), 256, GEMM_SMEM>>>(
        yh, wp, b_proj, out, nullptr, Mtok, Cdim, Cdim);
}

// round 11
// speedup vs baseline: 1.9255x; 1.0155x over previous
#include <cuda_runtime.h>
#include <cuda_fp16.h>
#include <cstdint>

// Problem constants
#define Cdim 2048
#define Sdim 2048
#define Bdim 4
#define Hdim 16
#define Ddim 128
#define Mtok (Bdim * Sdim)          // 8192
#define QKV_N (3 * Cdim)            // 6144

// ---------------------------------------------------------------------------
// Scratch (device globals — no allocation allowed)
// ---------------------------------------------------------------------------
__device__ __half g_qkvh[(size_t)Mtok * QKV_N];      // qkv (fp16)
__device__ __half g_xh[(size_t)Mtok * Cdim];         // x   (fp16)
__device__ __half g_yh[(size_t)Mtok * Cdim];         // y   (fp16)
__device__ __half g_wqkvT[(size_t)QKV_N * Cdim];     // [6144, 2048] (N,K) fp16
__device__ __half g_wprojT[(size_t)Cdim * Cdim];     // [2048, 2048] fp16

// ---------------------------------------------------------------------------
// PTX helpers (base-ISA only: cp.async / ldmatrix / mma.sync)
// ---------------------------------------------------------------------------
__device__ __forceinline__ uint32_t smem_u32(const void* p) {
    uint32_t a;
    asm("{ .reg .u64 t; cvta.to.shared.u64 t, %1; cvt.u32.u64 %0, t; }" : "=r"(a) : "l"(p));
    return a;
}

#define CP_ASYNC16(dst, src) \
    asm volatile("cp.async.cg.shared.global [%0], [%1], 16;" :: "r"(dst), "l"(src))
#define CP_COMMIT() asm volatile("cp.async.commit_group;" ::: "memory")
#define CP_WAIT(n)  asm volatile("cp.async.wait_group %0;" :: "n"(n) : "memory")

__device__ __forceinline__ void ldsm4(uint32_t* r, uint32_t addr) {
    asm volatile("ldmatrix.sync.aligned.m8n8.x4.shared.b16 {%0,%1,%2,%3}, [%4];"
                 : "=r"(r[0]), "=r"(r[1]), "=r"(r[2]), "=r"(r[3]) : "r"(addr));
}
__device__ __forceinline__ void ldsm4t(uint32_t* r, uint32_t addr) {
    asm volatile("ldmatrix.sync.aligned.m8n8.x4.trans.shared.b16 {%0,%1,%2,%3}, [%4];"
                 : "=r"(r[0]), "=r"(r[1]), "=r"(r[2]), "=r"(r[3]) : "r"(addr));
}

// fp16 MMA, fp32 accumulate
__device__ __forceinline__ void mma16816(float* d, const uint32_t* a,
                                         uint32_t b0, uint32_t b1) {
    asm volatile(
        "mma.sync.aligned.m16n8k16.row.col.f32.f16.f16.f32 "
        "{%0,%1,%2,%3}, {%4,%5,%6,%7}, {%8,%9}, {%0,%1,%2,%3};"
        : "+f"(d[0]), "+f"(d[1]), "+f"(d[2]), "+f"(d[3])
        : "r"(a[0]), "r"(a[1]), "r"(a[2]), "r"(a[3]), "r"(b0), "r"(b1));
}

// pack two fp32 -> fp16x2 (first arg in low half)
__device__ __forceinline__ uint32_t pack_f16(float lo, float hi) {
    uint32_t r;
    asm("cvt.rn.f16x2.f32 %0, %1, %2;" : "=r"(r) : "f"(hi), "f"(lo));
    return r;
}

// ---------------------------------------------------------------------------
// Conversion kernels (fp32 -> fp16)
// ---------------------------------------------------------------------------
__global__ void convert_h_kernel(const float* __restrict__ in,
                                 __half* __restrict__ hi, int n)
{
    int i = (blockIdx.x * blockDim.x + threadIdx.x) * 4;
    if (i >= n) return;
    float4 v = *(const float4*)(in + i);
    *(uint2*)(hi + i) = make_uint2(pack_f16(v.x, v.y), pack_f16(v.z, v.w));
}

// W [K, N] fp32 -> Wt [N, K] fp16
__global__ void transpose_h_kernel(const float* __restrict__ W,
                                   __half* __restrict__ Th, int K, int N)
{
    __shared__ float tile[32][33];
    int n0 = blockIdx.x * 32, k0 = blockIdx.y * 32;
    int tx = threadIdx.x, ty = threadIdx.y;   // 32 x 8
#pragma unroll
    for (int j = 0; j < 32; j += 8)
        tile[ty + j][tx] = W[(size_t)(k0 + ty + j) * N + n0 + tx];
    __syncthreads();
#pragma unroll
    for (int j = 0; j < 32; j += 8)
        Th[(size_t)(n0 + ty + j) * K + k0 + tx] = __float2half(tile[tx][ty + j]);
}

// ---------------------------------------------------------------------------
// fp16 single-pass GEMM: C[M,N] = A @ B^T + bias. CTA 128x128, BK=64,
// 8 warps (4m x 2n) 32x64 warp tiles, 3-stage cp.async, 2 CTAs/SM.
// OUTM=0: fp32 C.  OUTM=1: fp16 Ch.
// ---------------------------------------------------------------------------
#define GA_TILE 16384                      // 128 x 64 fp16
#define GSTAGE (2 * GA_TILE)               // A, B = 32768
#define GEMM_SMEM (3 * GSTAGE)             // 98304

template<int OUTM>
__global__ __launch_bounds__(256, 2) void gemm_mma_kernel(
    const __half* __restrict__ Ah,
    const __half* __restrict__ Bh,
    const float* __restrict__ bias, float* __restrict__ C,
    __half* __restrict__ Ch,
    int M, int N, int K)
{
    extern __shared__ char smem[];
    const uint32_t sbase = smem_u32(smem);

    const int t   = threadIdx.x;
    const int wid = t >> 5;
    const int lid = t & 31;
    const int n0  = blockIdx.x * 128;
    const int m0  = blockIdx.y * 128;
    const int wm  = (wid & 3) * 32;
    const int wn  = (wid >> 2) * 64;

    const __half* gA = Ah + (size_t)m0 * K;
    const __half* gB = Bh + (size_t)n0 * K;

    float acc[2][8][4];
#pragma unroll
    for (int mt = 0; mt < 2; ++mt)
#pragma unroll
        for (int nt = 0; nt < 8; ++nt)
#pragma unroll
            for (int e = 0; e < 4; ++e) acc[mt][nt][e] = 0.f;

    // Rows are 128B (64 fp16); swizzle: j ^ (row & 7) on 16B groups.
    auto load_stage = [&](int stage, int k0) {
        uint32_t sb = sbase + stage * GSTAGE;
        // A: 1024 segments, B: 1024 segments; 8 cp.async/thread
#pragma unroll
        for (int i = 0; i < 4; ++i) {
            int idx = t + i * 256;          // < 1024
            int row = idx >> 3, j = idx & 7;
            uint32_t dst = sb + row * 128 + ((j ^ (row & 7)) << 4);
            CP_ASYNC16(dst, gA + (size_t)row * K + k0 + j * 8);
            CP_ASYNC16(dst + GA_TILE, gB + (size_t)row * K + k0 + j * 8);
        }
    };

    const int lrow8 = (lid & 7) + ((lid >> 3) & 1) * 8;
    const int lk    = (lid >> 4) & 1;

    const int nk = K / 64;                  // 32 chunks
    load_stage(0, 0);  CP_COMMIT();
    load_stage(1, 64); CP_COMMIT();

    for (int c = 0; c < nk; ++c) {
        CP_WAIT(1);
        __syncthreads();
        if (c + 2 < nk) load_stage((c + 2) % 3, (c + 2) * 64);
        CP_COMMIT();

        const uint32_t sb = sbase + (c % 3) * GSTAGE;
        const uint32_t aH = sb, bH = sb + GA_TILE;

#pragma unroll
        for (int k16 = 0; k16 < 4; ++k16) {
            const int jg = k16 * 2 + lk;

            uint32_t bh[16];
#pragma unroll
            for (int nb = 0; nb < 4; ++nb) {
                int row = wn + nb * 16 + lrow8;
                uint32_t off = row * 128 + ((jg ^ (row & 7)) << 4);
                ldsm4(&bh[nb * 4], bH + off);
            }
#pragma unroll
            for (int mt = 0; mt < 2; ++mt) {
                int row = wm + mt * 16 + lrow8;
                uint32_t off = row * 128 + ((jg ^ (row & 7)) << 4);
                uint32_t ah[4];
                ldsm4(ah, aH + off);
#pragma unroll
                for (int nb = 0; nb < 4; ++nb) {
                    mma16816(acc[mt][2 * nb],     ah, bh[nb * 4 + 0], bh[nb * 4 + 2]);
                    mma16816(acc[mt][2 * nb + 1], ah, bh[nb * 4 + 1], bh[nb * 4 + 3]);
                }
            }
        }
    }

    const int gid = lid >> 2;
    const int tig = lid & 3;
#pragma unroll
    for (int mt = 0; mt < 2; ++mt) {
        int m = m0 + wm + mt * 16 + gid;
#pragma unroll
        for (int nt = 0; nt < 8; ++nt) {
            int n = n0 + wn + nt * 8 + tig * 2;
            float b0 = bias[n], b1 = bias[n + 1];
            float v00 = acc[mt][nt][0] + b0, v01 = acc[mt][nt][1] + b1;
            float v10 = acc[mt][nt][2] + b0, v11 = acc[mt][nt][3] + b1;
            if (OUTM == 0) {
                *(float2*)(C + (size_t)m * N + n)       = make_float2(v00, v01);
                *(float2*)(C + (size_t)(m + 8) * N + n) = make_float2(v10, v11);
            } else {
                *(uint32_t*)(Ch + (size_t)m * N + n)       = pack_f16(v00, v01);
                *(uint32_t*)(Ch + (size_t)(m + 8) * N + n) = pack_f16(v10, v11);
            }
        }
    }
}

// ---------------------------------------------------------------------------
// Flash attention, pure fp16 MMA operands, causal.
// CTA: 128 q-rows x 64-kv chunks. 8 warps x 16 q-rows. 2-stage KV pipeline,
// 96 KB smem -> 2 CTAs/SM (hides causal workload skew across qt).
// ---------------------------------------------------------------------------
#define KV_TILE_B 16384                     // 64 rows x 256 B
#define KV_STAGE_B (2 * KV_TILE_B)          // K, V
#define Q_TILE_B   32768                    // 128 rows x 256 B
#define ATTN_SMEM (Q_TILE_B + 2 * KV_STAGE_B)   // 98304

__global__ __launch_bounds__(256, 2) void attn_mma_kernel()
{
    extern __shared__ char sm8[];
    const uint32_t sb  = smem_u32(sm8);
    const uint32_t sQh = sb;
    const uint32_t sKV = sb + Q_TILE_B;

    const int t   = threadIdx.x;
    const int wid = t >> 5;
    const int lid = t & 31;
    const int qt  = blockIdx.x;
    const int h   = blockIdx.y;
    const int b   = blockIdx.z;
    const int m0  = qt * 128;
    const int wm  = wid * 16;
    const int gid = lid >> 2;
    const int tig = lid & 3;
    const int lrow8 = (lid & 7) + ((lid >> 3) & 1) * 8;
    const int lk    = (lid >> 4) & 1;

    const size_t tok0 = ((size_t)b * Sdim + m0) * QKV_N;
    const __half* qh = g_qkvh + tok0 + h * Ddim;
    const size_t kvtok = (size_t)b * Sdim * QKV_N;
    const __half* kv_base[2] = {
        g_qkvh + kvtok + Cdim + h * Ddim,      // K
        g_qkvh + kvtok + 2 * Cdim + h * Ddim   // V
    };

    auto load_kv = [&](int stage, int n0) {
        uint32_t dstb = sKV + stage * KV_STAGE_B;
#pragma unroll
        for (int i = 0; i < 8; ++i) {
            int idx  = t + i * 256;            // 0..2047
            int tile = idx >> 10;
            int rem  = idx & 1023;
            int row  = rem >> 4, j = rem & 15;
            const void* src = kv_base[tile] + (size_t)(n0 + row) * QKV_N + j * 8;
            uint32_t dst = dstb + tile * KV_TILE_B + row * 256 + ((j ^ (row & 7)) << 4);
            CP_ASYNC16(dst, src);
        }
    };

    const int ktmax = (m0 >> 6) + 1;

    // Q tile loads (group 0, with kv chunk 0)
#pragma unroll
    for (int i = 0; i < 8; ++i) {
        int idx  = t + i * 256;                // 0..2047
        int row  = idx >> 4, j = idx & 15;
        const __half* src = qh + (size_t)row * QKV_N + j * 8;
        uint32_t dst = sQh + row * 256 + ((j ^ (row & 7)) << 4);
        CP_ASYNC16(dst, src);
    }
    load_kv(0, 0);
    CP_COMMIT();                               // g0: Q + kv0
    if (ktmax >= 1) load_kv(1, 64);
    CP_COMMIT();

    float o[16][4];
    float m_i[2] = {-1e30f, -1e30f};
    float l_i[2] = {0.f, 0.f};
#pragma unroll
    for (int nt = 0; nt < 16; ++nt)
#pragma unroll
        for (int e = 0; e < 4; ++e) o[nt][e] = 0.f;

    const float scale = 0.08838834764831845f;   // 1/sqrt(128)
    const int r0g = m0 + wm + gid;

    for (int kt = 0; kt <= ktmax; ++kt) {
        const int n0 = kt << 6;
        CP_WAIT(1);
        __syncthreads();

        const uint32_t st  = sKV + (kt & 1) * KV_STAGE_B;
        const uint32_t sKh = st, sVh = st + KV_TILE_B;

        if (m0 + wm + 15 >= n0) {
            // ---- S = Q K^T ----
            float s[8][4];
#pragma unroll
            for (int nt = 0; nt < 8; ++nt)
#pragma unroll
                for (int e = 0; e < 4; ++e) s[nt][e] = 0.f;

#pragma unroll
            for (int ks = 0; ks < 8; ++ks) {
                const int jg = ks * 2 + lk;
                const int arow = wm + lrow8;
                uint32_t aoff = arow * 256 + ((jg ^ (arow & 7)) << 4);
                uint32_t qf[4];
                ldsm4(qf, sQh + aoff);
#pragma unroll
                for (int g = 0; g < 4; ++g) {
                    const int brow = g * 16 + lrow8;
                    uint32_t boff = brow * 256 + ((jg ^ (brow & 7)) << 4);
                    uint32_t kh[4];
                    ldsm4(kh, sKh + boff);
                    mma16816(s[2 * g],     qf, kh[0], kh[2]);
                    mma16816(s[2 * g + 1], qf, kh[1], kh[3]);
                }
            }

            // scale + causal mask
            const bool diag = (n0 + 63 > m0 + wm);
#pragma unroll
            for (int nt = 0; nt < 8; ++nt) {
                const int c0 = n0 + nt * 8 + tig * 2;
#pragma unroll
                for (int e = 0; e < 4; ++e) s[nt][e] *= scale;
                if (diag) {
                    if (c0     > r0g)     s[nt][0] = -1e30f;
                    if (c0 + 1 > r0g)     s[nt][1] = -1e30f;
                    if (c0     > r0g + 8) s[nt][2] = -1e30f;
                    if (c0 + 1 > r0g + 8) s[nt][3] = -1e30f;
                }
            }

            // ---- online softmax ----
#pragma unroll
            for (int rr = 0; rr < 2; ++rr) {
                float mx = -1e30f;
#pragma unroll
                for (int nt = 0; nt < 8; ++nt)
                    mx = fmaxf(mx, fmaxf(s[nt][2 * rr], s[nt][2 * rr + 1]));
                mx = fmaxf(mx, __shfl_xor_sync(0xffffffffu, mx, 1));
                mx = fmaxf(mx, __shfl_xor_sync(0xffffffffu, mx, 2));
                float m_new = fmaxf(m_i[rr], mx);
                float alpha = __expf(m_i[rr] - m_new);
                float sum = 0.f;
#pragma unroll
                for (int nt = 0; nt < 8; ++nt) {
                    float p0 = __expf(s[nt][2 * rr]     - m_new);
                    float p1 = __expf(s[nt][2 * rr + 1] - m_new);
                    s[nt][2 * rr]     = p0;
                    s[nt][2 * rr + 1] = p1;
                    sum += p0 + p1;
                }
                sum += __shfl_xor_sync(0xffffffffu, sum, 1);
                sum += __shfl_xor_sync(0xffffffffu, sum, 2);
                l_i[rr] = l_i[rr] * alpha + sum;
                m_i[rr] = m_new;
#pragma unroll
                for (int nt = 0; nt < 16; ++nt) {
                    o[nt][2 * rr]     *= alpha;
                    o[nt][2 * rr + 1] *= alpha;
                }
            }

            // ---- O += P V ----
#pragma unroll
            for (int j = 0; j < 4; ++j) {
                uint32_t ap[4];
#pragma unroll
                for (int half = 0; half < 2; ++half) {
                    const float* sp = s[2 * j + half];
                    ap[half * 2 + 0] = pack_f16(sp[0], sp[1]);
                    ap[half * 2 + 1] = pack_f16(sp[2], sp[3]);
                }
                const int vrow = j * 16 + lrow8;
#pragma unroll
                for (int g = 0; g < 8; ++g) {
                    const int jj = g * 2 + lk;
                    uint32_t voff = vrow * 256 + ((jj ^ (vrow & 7)) << 4);
                    uint32_t vh[4];
                    ldsm4t(vh, sVh + voff);
                    mma16816(o[2 * g],     ap, vh[0], vh[1]);
                    mma16816(o[2 * g + 1], ap, vh[2], vh[3]);
                }
            }
        }

        __syncthreads();
        if (kt + 2 <= ktmax) load_kv(kt & 1, (kt + 2) << 6);
        CP_COMMIT();
    }

    // ---- epilogue: normalize, write fp16 y ----
    const float inv0 = 1.0f / l_i[0];
    const float inv1 = 1.0f / l_i[1];
    const size_t ybase = (size_t)b * Sdim * Cdim + (size_t)h * Ddim;
    __half* yh = g_yh + ybase;
    const size_t row0 = (size_t)(m0 + wm + gid) * Cdim;
    const size_t row1 = row0 + 8 * Cdim;
#pragma unroll
    for (int nt = 0; nt < 16; ++nt) {
        const int col = nt * 8 + tig * 2;
        *(uint32_t*)(yh + row0 + col) = pack_f16(o[nt][0] * inv0, o[nt][1] * inv0);
        *(uint32_t*)(yh + row1 + col) = pack_f16(o[nt][2] * inv1, o[nt][3] * inv1);
    }
}

// ---------------------------------------------------------------------------
// Launch
// ---------------------------------------------------------------------------
extern "C" void kernel_launch(void* const* d_in, const int* in_sizes, int n_in,
                              void* d_out, int out_size)
{
    const float* x      = (const float*)d_in[0];
    const float* w_qkv  = (const float*)d_in[1];
    const float* b_qkv  = (const float*)d_in[2];
    const float* w_proj = (const float*)d_in[3];
    const float* b_proj = (const float*)d_in[4];
    float* out = (float*)d_out;

    __half *qkvh, *xh, *yh, *wq, *wp;
    cudaGetSymbolAddress((void**)&qkvh, g_qkvh);
    cudaGetSymbolAddress((void**)&xh,  g_xh);
    cudaGetSymbolAddress((void**)&yh,  g_yh);
    cudaGetSymbolAddress((void**)&wq,  g_wqkvT);
    cudaGetSymbolAddress((void**)&wp,  g_wprojT);

    cudaFuncSetAttribute(gemm_mma_kernel<0>,
                         cudaFuncAttributeMaxDynamicSharedMemorySize, GEMM_SMEM);
    cudaFuncSetAttribute(gemm_mma_kernel<1>,
                         cudaFuncAttributeMaxDynamicSharedMemorySize, GEMM_SMEM);
    cudaFuncSetAttribute(attn_mma_kernel,
                         cudaFuncAttributeMaxDynamicSharedMemorySize, ATTN_SMEM);

    // 1) input convert / weight transposes (fp16)
    {
        int n = Mtok * Cdim;
        convert_h_kernel<<<(n / 4 + 255) / 256, 256>>>(x, xh, n);
    }
    transpose_h_kernel<<<dim3(QKV_N / 32, Cdim / 32), dim3(32, 8)>>>(
        w_qkv, wq, Cdim, QKV_N);
    transpose_h_kernel<<<dim3(Cdim / 32, Cdim / 32), dim3(32, 8)>>>(
        w_proj, wp, Cdim, Cdim);

    // 2) qkv = x @ w_qkv + b_qkv   [8192, 6144] -> fp16
    gemm_mma_kernel<1><<<dim3(QKV_N / 128, Mtok / 128), 256, GEMM_SMEM>>>(
        xh, wq, b_qkv, nullptr, qkvh, Mtok, QKV_N, Cdim);

    // 3) flash attention (fp16) -> yh
    {
        dim3 grid(Sdim / 128, Hdim, Bdim);
        attn_mma_kernel<<<grid, 256, ATTN_SMEM>>>();
    }

    // 4) out = y @ w_proj + b_proj   [8192, 2048] fp32
    gemm_mma_kernel<0><<<dim3(Cdim / 128, Mtok / 128), 256, GEMM_SMEM>>>(
        yh, wp, b_proj, out, nullptr, Mtok, Cdim, Cdim);
}